// round 5
// baseline (speedup 1.0000x reference)
#include <cuda_runtime.h>
#include <cstdint>

#define Nn 50000
#define Ee 640000
#define INDIM 128
#define Hh 4
#define Cc 32
#define Rr 8
#define HC 128
#define NSEG (Rr*Nn)          // 400000
#define SCAN_B 1024
#define SCAN_NB ((NSEG + SCAN_B - 1)/SCAN_B)   // 391

// ---------------- device scratch ----------------------------------------------
__device__ __align__(16) float g_hj[(size_t)Nn*HC];
__device__ __align__(16) float g_hi[(size_t)Nn*HC];
__device__ __align__(16) float g_selfnode[(size_t)Nn*HC];
__device__ __align__(16) float g_selfterm[(size_t)Nn*Cc];
__device__ float g_ai[(size_t)Nn*Rr*Hh];
__device__ float g_aj[(size_t)Nn*Rr*Hh];
__device__ float g_q[(size_t)NSEG*Cc];
__device__ float g_k[(size_t)NSEG*Cc];
__device__ float g_v[(size_t)NSEG*Cc];
// edge arrays + sort scratch
__device__ int g_src[Ee];
__device__ int g_dst[Ee];
__device__ int g_rel[Ee];
__device__ int g_hist[NSEG];
__device__ int g_fill[NSEG];
__device__ int g_off[NSEG+1];
__device__ int g_bsum[SCAN_NB];
__device__ int g_boff[SCAN_NB];
__device__ int g_ssrc[Ee];        // src node id, sorted by segment
__device__ int g_is64;

// ---------------- K_detect ----------------------------------------------------
__global__ void k_detect(const int* __restrict__ ei_raw) {
    if (threadIdx.x == 0 && blockIdx.x == 0) {
        int allzero = 1;
        for (int i = 1; i < 256; i += 2)
            if (ei_raw[i] != 0) { allzero = 0; break; }
        g_is64 = allzero;
    }
}

// ---------------- K_zero ------------------------------------------------------
__global__ void k_zero() {
    int i = blockIdx.x * blockDim.x + threadIdx.x;
    int stride = gridDim.x * blockDim.x;
    for (int j = i; j < NSEG; j += stride) { g_hist[j] = 0; g_fill[j] = 0; }
}

// ---------------- K_convert: normalize edges + histogram ----------------------
__global__ void k_convert(const void* __restrict__ ei_raw,
                          const void* __restrict__ et_raw) {
    int e = blockIdx.x * blockDim.x + threadIdx.x;
    if (e >= Ee) return;
    int s, d, r;
    if (g_is64) {
        const long long* ei = (const long long*)ei_raw;
        const long long* et = (const long long*)et_raw;
        s = (int)ei[e]; d = (int)ei[Ee + e]; r = (int)et[e];
    } else {
        const int* ei = (const int*)ei_raw;
        const int* et = (const int*)et_raw;
        s = ei[e]; d = ei[Ee + e]; r = et[e];
    }
    g_src[e] = s; g_dst[e] = d; g_rel[e] = r;
    atomicAdd(&g_hist[r*Nn + d], 1);
}

// ---------------- scan (3 kernels) --------------------------------------------
__global__ void k_scan1() {
    __shared__ int sh[SCAN_B];
    int t = threadIdx.x;
    int i = blockIdx.x * SCAN_B + t;
    int v = (i < NSEG) ? g_hist[i] : 0;
    sh[t] = v;
    __syncthreads();
    for (int off = 1; off < SCAN_B; off <<= 1) {
        int t2 = (t >= off) ? sh[t - off] : 0;
        __syncthreads();
        if (t >= off) sh[t] += t2;
        __syncthreads();
    }
    if (i < NSEG) g_off[i] = sh[t] - v;
    if (t == SCAN_B - 1) g_bsum[blockIdx.x] = sh[t];
}
__global__ void k_scan2() {
    __shared__ int sh[512];
    int t = threadIdx.x;
    int v = (t < SCAN_NB) ? g_bsum[t] : 0;
    sh[t] = v;
    __syncthreads();
    for (int off = 1; off < 512; off <<= 1) {
        int t2 = (t >= off) ? sh[t - off] : 0;
        __syncthreads();
        if (t >= off) sh[t] += t2;
        __syncthreads();
    }
    if (t < SCAN_NB) g_boff[t] = sh[t] - v;
}
__global__ void k_scan3() {
    int t = threadIdx.x;
    int i = blockIdx.x * SCAN_B + t;
    if (i < NSEG) g_off[i] += g_boff[blockIdx.x];
    if (i == 0) g_off[NSEG] = Ee;
}

// ---------------- K_reorder: counting-sort; store SRC id directly -------------
__global__ void k_reorder() {
    int e = blockIdx.x * blockDim.x + threadIdx.x;
    if (e >= Ee) return;
    int seg = g_rel[e]*Nn + g_dst[e];
    int pos = g_off[seg] + atomicAdd(&g_fill[seg], 1);
    g_ssrc[pos] = g_src[e];
}

// ---------------- K1: input GEMM x[N,128] @ {Wj,Wi,Wsn,Wself} -----------------
__global__ void __launch_bounds__(256) k_gemm_x(
        const float* __restrict__ x,
        const float* __restrict__ Wj,
        const float* __restrict__ Wi,
        const float* __restrict__ Wsn,
        const float* __restrict__ Wself) {
    int mat = blockIdx.z;
    int width = (mat == 3) ? Cc : HC;
    int col0 = blockIdx.x * 64;
    if (col0 >= width) return;
    int row0 = blockIdx.y * 128;
    const float* W = (mat==0) ? Wj : (mat==1) ? Wi : (mat==2) ? Wsn : Wself;
    float* out = (mat==0) ? g_hj : (mat==1) ? g_hi : (mat==2) ? g_selfnode : g_selfterm;

    __shared__ float zs[128][17];
    __shared__ alignas(16) float ws[16][68];
    int tid = threadIdx.x;
    int tx = tid & 15, ty = tid >> 4;
    float acc[8][4] = {};

    for (int kb = 0; kb < INDIM; kb += 16) {
        #pragma unroll
        for (int i = 0; i < 8; i++) {
            int idx = tid + i*256;
            int rr = idx >> 4, kk = idx & 15;
            int gr = row0 + rr;
            zs[rr][kk] = (gr < Nn) ? x[(size_t)gr*INDIM + kb + kk] : 0.f;
        }
        #pragma unroll
        for (int i = 0; i < 4; i++) {
            int idx = tid + i*256;
            int kk = idx >> 6, cc = idx & 63;
            int gc = col0 + cc;
            ws[kk][cc] = (gc < width) ? W[(size_t)(kb+kk)*width + gc] : 0.f;
        }
        __syncthreads();
        #pragma unroll
        for (int k = 0; k < 16; k++) {
            float4 b4 = *(const float4*)&ws[k][tx*4];
            float b[4] = {b4.x, b4.y, b4.z, b4.w};
            #pragma unroll
            for (int i = 0; i < 8; i++) {
                float a = zs[ty*8+i][k];
                #pragma unroll
                for (int j = 0; j < 4; j++)
                    acc[i][j] = fmaf(a, b[j], acc[i][j]);
            }
        }
        __syncthreads();
    }
    #pragma unroll
    for (int i = 0; i < 8; i++) {
        int gr = row0 + ty*8 + i;
        if (gr >= Nn) continue;
        #pragma unroll
        for (int j = 0; j < 4; j++) {
            int gc = col0 + tx*4 + j;
            if (gc < width) out[(size_t)gr*width + gc] = acc[i][j];
        }
    }
}

// ---------------- K2: per-node attention coefficients -------------------------
__global__ void k_attcoef(const float* __restrict__ node_att) {
    int idx = blockIdx.x * blockDim.x + threadIdx.x;
    if (idx >= Nn*32) return;
    int n = idx >> 5, p = idx & 31;
    int h = p & 3;
    const float* att = node_att + p*64;
    const float* hi = g_hi + (size_t)n*HC + h*Cc;
    const float* hj = g_hj + (size_t)n*HC + h*Cc;
    float si = 0.f, sj = 0.f;
    #pragma unroll
    for (int c = 0; c < 32; c++) {
        si = fmaf(att[c],    hi[c], si);
        sj = fmaf(att[32+c], hj[c], sj);
    }
    g_ai[idx] = si;
    g_aj[idx] = sj;
}

// ---------------- K_seg_qkv: fused segment softmax-aggregate + QKV GEMM -------
// Block = (64 consecutive nodes, one relation). Phase 1: aggregate z into smem.
// Phase 2: z[64,128] @ W[128,96] -> q,k,v.
__global__ void __launch_bounds__(256) k_seg_qkv(
        const float* __restrict__ Wq,
        const float* __restrict__ Wk,
        const float* __restrict__ Wv) {
    int r = blockIdx.y;
    int n0 = blockIdx.x * 64;
    __shared__ float zs[64][132];
    __shared__ float ws[16][100];
    int tid = threadIdx.x;
    int l = tid & 31, wid = tid >> 5;

    // ---- phase 1: warp per segment (8 warps x 8 segments) ----
    for (int i = wid; i < 64; i += 8) {
        int n = n0 + i;
        if (n >= Nn) {
            #pragma unroll
            for (int c = 0; c < 4; c++) zs[i][l*4 + c] = 0.f;
            continue;
        }
        int w = r*Nn + n;
        int begin = g_off[w], end = g_off[w+1];
        int h = l >> 3;
        float ain = g_ai[n*32 + r*4 + h];
        float m = __int_as_float(0xff800000);
        for (int p = begin; p < end; p++) {
            int s = g_ssrc[p];
            float a = ain + g_aj[s*32 + r*4 + h];
            a = (a >= 0.f) ? a : 0.2f*a;
            m = fmaxf(m, a);
        }
        float sumex = 0.f;
        float4 acc = make_float4(0.f, 0.f, 0.f, 0.f);
        for (int p = begin; p < end; p++) {
            int s = g_ssrc[p];
            float a = ain + g_aj[s*32 + r*4 + h];
            a = (a >= 0.f) ? a : 0.2f*a;
            float ex = __expf(a - m);
            sumex += ex;
            float4 xj = ((const float4*)(g_hj + (size_t)s*HC))[l];
            acc.x = fmaf(ex, xj.x, acc.x);
            acc.y = fmaf(ex, xj.y, acc.y);
            acc.z = fmaf(ex, xj.z, acc.z);
            acc.w = fmaf(ex, xj.w, acc.w);
        }
        float inv = 1.f / (sumex + 1e-16f);
        float4 self = ((const float4*)(g_selfnode + (size_t)n*HC))[l];
        zs[i][l*4+0] = fmaf(acc.x, inv, self.x);
        zs[i][l*4+1] = fmaf(acc.y, inv, self.y);
        zs[i][l*4+2] = fmaf(acc.z, inv, self.z);
        zs[i][l*4+3] = fmaf(acc.w, inv, self.w);
    }
    __syncthreads();

    // ---- phase 2: GEMM zs[64,128] @ W[128,96] ----
    int tx = tid & 15, ty = tid >> 4;       // tx: 16 col-groups of 6, ty: 16 row-groups of 4
    float acc[4][6] = {};
    for (int kb = 0; kb < INDIM; kb += 16) {
        #pragma unroll
        for (int i = 0; i < 6; i++) {
            int idx = tid + i*256;          // 1536 = 16*96
            int kk = idx / 96, cc = idx - kk*96;
            int sel = cc >> 5, lc = cc & 31;
            const float* Wsel = (sel==0) ? Wq : (sel==1) ? Wk : Wv;
            ws[kk][cc] = Wsel[(size_t)r*4096 + (kb+kk)*32 + lc];
        }
        __syncthreads();
        #pragma unroll
        for (int k = 0; k < 16; k++) {
            float b[6];
            #pragma unroll
            for (int j = 0; j < 6; j++) b[j] = ws[k][tx*6 + j];
            #pragma unroll
            for (int i = 0; i < 4; i++) {
                float a = zs[ty*4+i][kb+k];
                #pragma unroll
                for (int j = 0; j < 6; j++)
                    acc[i][j] = fmaf(a, b[j], acc[i][j]);
            }
        }
        __syncthreads();
    }
    #pragma unroll
    for (int i = 0; i < 4; i++) {
        int gr = n0 + ty*4 + i;
        if (gr >= Nn) continue;
        #pragma unroll
        for (int j = 0; j < 6; j++) {
            int gc = tx*6 + j;
            int sel = gc >> 5, lc = gc & 31;
            float* o = (sel==0) ? g_q : (sel==1) ? g_k : g_v;
            o[((size_t)(r*Nn + gr))*Cc + lc] = acc[i][j];
        }
    }
}

// ---------------- K7: relation attention + output (warp per node) -------------
__global__ void k_final(const float* __restrict__ Wrel, float* __restrict__ out) {
    int w = (blockIdx.x * blockDim.x + threadIdx.x) >> 5;
    int l = threadIdx.x & 31;
    if (w >= Nn) return;
    int n = w;
    float q[Rr], kk[Rr], vv[Rr];
    #pragma unroll
    for (int r = 0; r < Rr; r++) {
        int base = (r*Nn + n)*Cc + l;
        q[r]  = g_q[base];
        kk[r] = g_k[base];
        vv[r] = g_v[base];
    }
    float st = g_selfterm[(size_t)n*Cc + l];
    float acc = 0.f;
    #pragma unroll
    for (int r = 0; r < Rr; r++) {
        float p[Rr];
        #pragma unroll
        for (int s = 0; s < Rr; s++) {
            float t = q[r] * kk[s];
            #pragma unroll
            for (int o = 16; o > 0; o >>= 1) t += __shfl_xor_sync(0xffffffffu, t, o);
            p[s] = t;
        }
        float m = p[0];
        #pragma unroll
        for (int s = 1; s < Rr; s++) m = fmaxf(m, p[s]);
        float sum = 0.f;
        #pragma unroll
        for (int s = 0; s < Rr; s++) { p[s] = expf(p[s] - m); sum += p[s]; }
        float inv = 1.f / sum;
        float delta = 0.f;
        #pragma unroll
        for (int s = 0; s < Rr; s++) delta = fmaf(p[s]*inv, vv[s], delta);
        float sd = delta;
        #pragma unroll
        for (int o = 16; o > 0; o >>= 1) sd += __shfl_xor_sync(0xffffffffu, sd, o);
        float mask = (sd != 0.f) ? 1.f : 0.f;
        acc = fmaf(Wrel[r], delta + st*mask, acc);
    }
    out[(size_t)n*Cc + l] = acc;
}

// ---------------- launcher ----------------------------------------------------
extern "C" void kernel_launch(void* const* d_in, const int* in_sizes, int n_in,
                              void* d_out, int out_size) {
    const float* x     = (const float*)d_in[0];
    const void*  ei    = d_in[1];
    const void*  et    = d_in[2];
    const float* Wj    = (const float*)d_in[3];
    const float* Wi    = (const float*)d_in[4];
    const float* natt  = (const float*)d_in[5];
    const float* Wq    = (const float*)d_in[6];
    const float* Wk    = (const float*)d_in[7];
    const float* Wv    = (const float*)d_in[8];
    const float* Wself = (const float*)d_in[9];
    const float* Wsn   = (const float*)d_in[10];
    const float* Wrel  = (const float*)d_in[11];
    float* out = (float*)d_out;

    k_detect<<<1, 32>>>((const int*)ei);
    k_zero<<<400, 256>>>();
    k_convert<<<(Ee + 255)/256, 256>>>(ei, et);
    k_scan1<<<SCAN_NB, SCAN_B>>>();
    k_scan2<<<1, 512>>>();
    k_scan3<<<SCAN_NB, SCAN_B>>>();
    k_reorder<<<(Ee + 255)/256, 256>>>();

    k_gemm_x<<<dim3(2, (Nn + 127)/128, 4), 256>>>(x, Wj, Wi, Wsn, Wself);
    k_attcoef<<<(Nn*32 + 255)/256, 256>>>(natt);
    k_seg_qkv<<<dim3((Nn + 63)/64, Rr), 256>>>(Wq, Wk, Wv);
    k_final<<<(Nn + 7)/8, 256>>>(Wrel, out);
}

// round 6
// speedup vs baseline: 1.5314x; 1.5314x over previous
#include <cuda_runtime.h>
#include <cstdint>

#define Nn 50000
#define Ee 640000
#define INDIM 128
#define Hh 4
#define Cc 32
#define Rr 8
#define HC 128
#define NSEG (Rr*Nn)          // 400000
#define SCAN_B 1024
#define SCAN_NB ((NSEG + SCAN_B - 1)/SCAN_B)   // 391

// ---------------- device scratch ----------------------------------------------
__device__ __align__(16) float g_hj[(size_t)Nn*HC];
__device__ __align__(16) float g_hi[(size_t)Nn*HC];
__device__ __align__(16) float g_selfnode[(size_t)Nn*HC];
__device__ __align__(16) float g_selfterm[(size_t)Nn*Cc];
__device__ __align__(16) float g_ai[(size_t)Nn*Rr*Hh];
__device__ __align__(16) float g_aj[(size_t)Nn*Rr*Hh];
__device__ __align__(16) float g_z[(size_t)NSEG*HC];     // 204.8MB
__device__ float g_q[(size_t)NSEG*Cc];
__device__ float g_k[(size_t)NSEG*Cc];
__device__ float g_v[(size_t)NSEG*Cc];
// edge arrays + sort scratch
__device__ int g_src[Ee];
__device__ int g_dst[Ee];
__device__ int g_rel[Ee];
__device__ int g_hist[NSEG];
__device__ int g_fill[NSEG];
__device__ int g_off[NSEG+1];
__device__ int g_bsum[SCAN_NB];
__device__ int g_boff[SCAN_NB];
__device__ int g_ssrc[Ee];                       // src node id, sorted by segment
__device__ __align__(16) float g_salpha[(size_t)Ee*4];  // per-edge 4-head alpha, sorted
__device__ int g_is64;

// ---------------- K_detect ----------------------------------------------------
__global__ void k_detect(const int* __restrict__ ei_raw) {
    if (threadIdx.x == 0 && blockIdx.x == 0) {
        int allzero = 1;
        for (int i = 1; i < 256; i += 2)
            if (ei_raw[i] != 0) { allzero = 0; break; }
        g_is64 = allzero;
    }
}

// ---------------- K_zero ------------------------------------------------------
__global__ void k_zero() {
    int i = blockIdx.x * blockDim.x + threadIdx.x;
    int stride = gridDim.x * blockDim.x;
    for (int j = i; j < NSEG; j += stride) { g_hist[j] = 0; g_fill[j] = 0; }
}

// ---------------- K_convert: normalize edges + histogram ----------------------
__global__ void k_convert(const void* __restrict__ ei_raw,
                          const void* __restrict__ et_raw) {
    int e = blockIdx.x * blockDim.x + threadIdx.x;
    if (e >= Ee) return;
    int s, d, r;
    if (g_is64) {
        const long long* ei = (const long long*)ei_raw;
        const long long* et = (const long long*)et_raw;
        s = (int)ei[e]; d = (int)ei[Ee + e]; r = (int)et[e];
    } else {
        const int* ei = (const int*)ei_raw;
        const int* et = (const int*)et_raw;
        s = ei[e]; d = ei[Ee + e]; r = et[e];
    }
    g_src[e] = s; g_dst[e] = d; g_rel[e] = r;
    atomicAdd(&g_hist[r*Nn + d], 1);
}

// ---------------- scan (3 kernels) --------------------------------------------
__global__ void k_scan1() {
    __shared__ int sh[SCAN_B];
    int t = threadIdx.x;
    int i = blockIdx.x * SCAN_B + t;
    int v = (i < NSEG) ? g_hist[i] : 0;
    sh[t] = v;
    __syncthreads();
    for (int off = 1; off < SCAN_B; off <<= 1) {
        int t2 = (t >= off) ? sh[t - off] : 0;
        __syncthreads();
        if (t >= off) sh[t] += t2;
        __syncthreads();
    }
    if (i < NSEG) g_off[i] = sh[t] - v;
    if (t == SCAN_B - 1) g_bsum[blockIdx.x] = sh[t];
}
__global__ void k_scan2() {
    __shared__ int sh[512];
    int t = threadIdx.x;
    int v = (t < SCAN_NB) ? g_bsum[t] : 0;
    sh[t] = v;
    __syncthreads();
    for (int off = 1; off < 512; off <<= 1) {
        int t2 = (t >= off) ? sh[t - off] : 0;
        __syncthreads();
        if (t >= off) sh[t] += t2;
        __syncthreads();
    }
    if (t < SCAN_NB) g_boff[t] = sh[t] - v;
}
__global__ void k_scan3() {
    int t = threadIdx.x;
    int i = blockIdx.x * SCAN_B + t;
    if (i < NSEG) g_off[i] += g_boff[blockIdx.x];
    if (i == 0) g_off[NSEG] = Ee;
}

// ---------------- K_reorder: counting-sort + precompute edge alphas -----------
__global__ void k_reorder() {
    int e = blockIdx.x * blockDim.x + threadIdx.x;
    if (e >= Ee) return;
    int s = g_src[e], d = g_dst[e], r = g_rel[e];
    int seg = r*Nn + d;
    int pos = g_off[seg] + atomicAdd(&g_fill[seg], 1);
    g_ssrc[pos] = s;
    float4 ai = *(const float4*)&g_ai[d*32 + r*4];
    float4 aj = *(const float4*)&g_aj[s*32 + r*4];
    float4 a;
    a.x = ai.x + aj.x; a.y = ai.y + aj.y; a.z = ai.z + aj.z; a.w = ai.w + aj.w;
    a.x = (a.x >= 0.f) ? a.x : 0.2f*a.x;
    a.y = (a.y >= 0.f) ? a.y : 0.2f*a.y;
    a.z = (a.z >= 0.f) ? a.z : 0.2f*a.z;
    a.w = (a.w >= 0.f) ? a.w : 0.2f*a.w;
    ((float4*)g_salpha)[pos] = a;
}

// ---------------- K1: input GEMM x[N,128] @ {Wj,Wi,Wsn,Wself} -----------------
__global__ void __launch_bounds__(256) k_gemm_x(
        const float* __restrict__ x,
        const float* __restrict__ Wj,
        const float* __restrict__ Wi,
        const float* __restrict__ Wsn,
        const float* __restrict__ Wself) {
    int mat = blockIdx.z;
    int width = (mat == 3) ? Cc : HC;
    int col0 = blockIdx.x * 64;
    if (col0 >= width) return;
    int row0 = blockIdx.y * 128;
    const float* W = (mat==0) ? Wj : (mat==1) ? Wi : (mat==2) ? Wsn : Wself;
    float* out = (mat==0) ? g_hj : (mat==1) ? g_hi : (mat==2) ? g_selfnode : g_selfterm;

    __shared__ float zs[128][17];
    __shared__ alignas(16) float ws[16][68];
    int tid = threadIdx.x;
    int tx = tid & 15, ty = tid >> 4;
    float acc[8][4] = {};

    for (int kb = 0; kb < INDIM; kb += 16) {
        #pragma unroll
        for (int i = 0; i < 8; i++) {
            int idx = tid + i*256;
            int rr = idx >> 4, kk = idx & 15;
            int gr = row0 + rr;
            zs[rr][kk] = (gr < Nn) ? x[(size_t)gr*INDIM + kb + kk] : 0.f;
        }
        #pragma unroll
        for (int i = 0; i < 4; i++) {
            int idx = tid + i*256;
            int kk = idx >> 6, cc = idx & 63;
            int gc = col0 + cc;
            ws[kk][cc] = (gc < width) ? W[(size_t)(kb+kk)*width + gc] : 0.f;
        }
        __syncthreads();
        #pragma unroll
        for (int k = 0; k < 16; k++) {
            float4 b4 = *(const float4*)&ws[k][tx*4];
            float b[4] = {b4.x, b4.y, b4.z, b4.w};
            #pragma unroll
            for (int i = 0; i < 8; i++) {
                float a = zs[ty*8+i][k];
                #pragma unroll
                for (int j = 0; j < 4; j++)
                    acc[i][j] = fmaf(a, b[j], acc[i][j]);
            }
        }
        __syncthreads();
    }
    #pragma unroll
    for (int i = 0; i < 8; i++) {
        int gr = row0 + ty*8 + i;
        if (gr >= Nn) continue;
        #pragma unroll
        for (int j = 0; j < 4; j++) {
            int gc = col0 + tx*4 + j;
            if (gc < width) out[(size_t)gr*width + gc] = acc[i][j];
        }
    }
}

// ---------------- K2: per-node attention coefficients -------------------------
__global__ void k_attcoef(const float* __restrict__ node_att) {
    int idx = blockIdx.x * blockDim.x + threadIdx.x;
    if (idx >= Nn*32) return;
    int n = idx >> 5, p = idx & 31;
    int h = p & 3;
    const float* att = node_att + p*64;
    const float* hi = g_hi + (size_t)n*HC + h*Cc;
    const float* hj = g_hj + (size_t)n*HC + h*Cc;
    float si = 0.f, sj = 0.f;
    #pragma unroll
    for (int c = 0; c < 32; c++) {
        si = fmaf(att[c],    hi[c], si);
        sj = fmaf(att[32+c], hj[c], sj);
    }
    g_ai[idx] = si;
    g_aj[idx] = sj;
}

// ---------------- K_seg: warp per segment — softmax + aggregate + selfnode ----
__global__ void k_seg() {
    int w = (blockIdx.x * blockDim.x + threadIdx.x) >> 5;
    if (w >= NSEG) return;
    int l = threadIdx.x & 31;
    int r = w / Nn;
    int n = w - r*Nn;
    int begin = g_off[w], end = g_off[w+1];

    if (begin == end) {
        // empty segment: z = selfnode row
        float4 self = ((const float4*)(g_selfnode + (size_t)n*HC))[l];
        ((float4*)(g_z + (size_t)w*HC))[l] = self;
        return;
    }

    int h = l >> 3, j = l & 7;
    // pass 1: lane-parallel max over precomputed alphas (coalesced)
    float m = __int_as_float(0xff800000);
    for (int p = begin + j; p < end; p += 8)
        m = fmaxf(m, g_salpha[(size_t)p*4 + h]);
    #pragma unroll
    for (int o = 1; o < 8; o <<= 1)
        m = fmaxf(m, __shfl_xor_sync(0xffffffffu, m, o));

    // pass 2: exp-sum + weighted gather-accumulate (one gather chain per edge)
    float sumex = 0.f;
    float4 acc = make_float4(0.f, 0.f, 0.f, 0.f);
    for (int p = begin; p < end; p++) {
        float a = g_salpha[(size_t)p*4 + h];
        float ex = __expf(a - m);
        sumex += ex;
        int s = g_ssrc[p];
        float4 xj = ((const float4*)(g_hj + (size_t)s*HC))[l];
        acc.x = fmaf(ex, xj.x, acc.x);
        acc.y = fmaf(ex, xj.y, acc.y);
        acc.z = fmaf(ex, xj.z, acc.z);
        acc.w = fmaf(ex, xj.w, acc.w);
    }
    float inv = 1.f / (sumex + 1e-16f);
    float4 self = ((const float4*)(g_selfnode + (size_t)n*HC))[l];
    float4 zv;
    zv.x = fmaf(acc.x, inv, self.x);
    zv.y = fmaf(acc.y, inv, self.y);
    zv.z = fmaf(acc.z, inv, self.z);
    zv.w = fmaf(acc.w, inv, self.w);
    ((float4*)(g_z + (size_t)w*HC))[l] = zv;
}

// ---------------- K6: per-relation QKV GEMM  z[N,128]@[128,96] ----------------
__global__ void __launch_bounds__(256) k_qkv(
        const float* __restrict__ Wq,
        const float* __restrict__ Wk,
        const float* __restrict__ Wv) {
    int r = blockIdx.y;
    int row0 = blockIdx.x * 128;
    __shared__ float zs[128][17];
    __shared__ alignas(16) float ws[16][98];
    int tid = threadIdx.x;
    int tx = tid & 15, ty = tid >> 4;
    float acc[8][6] = {};

    for (int kb = 0; kb < INDIM; kb += 16) {
        #pragma unroll
        for (int i = 0; i < 8; i++) {
            int idx = tid + i*256;
            int rr = idx >> 4, kk = idx & 15;
            int gr = row0 + rr;
            zs[rr][kk] = (gr < Nn) ? g_z[((size_t)(r*Nn + gr))*HC + kb + kk] : 0.f;
        }
        #pragma unroll
        for (int i = 0; i < 6; i++) {
            int idx = tid + i*256;          // 1536 = 16*96
            int kk = idx / 96, cc = idx - kk*96;
            int sel = cc >> 5, lc = cc & 31;
            const float* Wsel = (sel==0) ? Wq : (sel==1) ? Wk : Wv;
            ws[kk][cc] = Wsel[(size_t)r*4096 + (kb+kk)*32 + lc];
        }
        __syncthreads();
        #pragma unroll
        for (int k = 0; k < 16; k++) {
            float b[6];
            float2 b0 = *(const float2*)&ws[k][tx*6 + 0];
            float2 b1 = *(const float2*)&ws[k][tx*6 + 2];
            float2 b2 = *(const float2*)&ws[k][tx*6 + 4];
            b[0]=b0.x; b[1]=b0.y; b[2]=b1.x; b[3]=b1.y; b[4]=b2.x; b[5]=b2.y;
            #pragma unroll
            for (int i = 0; i < 8; i++) {
                float a = zs[ty*8+i][k];
                #pragma unroll
                for (int j = 0; j < 6; j++)
                    acc[i][j] = fmaf(a, b[j], acc[i][j]);
            }
        }
        __syncthreads();
    }
    #pragma unroll
    for (int i = 0; i < 8; i++) {
        int gr = row0 + ty*8 + i;
        if (gr >= Nn) continue;
        #pragma unroll
        for (int j = 0; j < 6; j++) {
            int gc = tx*6 + j;
            int sel = gc >> 5, lc = gc & 31;
            float* o = (sel==0) ? g_q : (sel==1) ? g_k : g_v;
            o[((size_t)(r*Nn + gr))*Cc + lc] = acc[i][j];
        }
    }
}

// ---------------- K7: relation attention + output (warp per node) -------------
__global__ void k_final(const float* __restrict__ Wrel, float* __restrict__ out) {
    int w = (blockIdx.x * blockDim.x + threadIdx.x) >> 5;
    int l = threadIdx.x & 31;
    if (w >= Nn) return;
    int n = w;
    float q[Rr], kk[Rr], vv[Rr];
    #pragma unroll
    for (int r = 0; r < Rr; r++) {
        int base = (r*Nn + n)*Cc + l;
        q[r]  = g_q[base];
        kk[r] = g_k[base];
        vv[r] = g_v[base];
    }
    float st = g_selfterm[(size_t)n*Cc + l];
    float acc = 0.f;
    #pragma unroll
    for (int r = 0; r < Rr; r++) {
        float p[Rr];
        #pragma unroll
        for (int s = 0; s < Rr; s++) {
            float t = q[r] * kk[s];
            #pragma unroll
            for (int o = 16; o > 0; o >>= 1) t += __shfl_xor_sync(0xffffffffu, t, o);
            p[s] = t;
        }
        float m = p[0];
        #pragma unroll
        for (int s = 1; s < Rr; s++) m = fmaxf(m, p[s]);
        float sum = 0.f;
        #pragma unroll
        for (int s = 0; s < Rr; s++) { p[s] = expf(p[s] - m); sum += p[s]; }
        float inv = 1.f / sum;
        float delta = 0.f;
        #pragma unroll
        for (int s = 0; s < Rr; s++) delta = fmaf(p[s]*inv, vv[s], delta);
        float sd = delta;
        #pragma unroll
        for (int o = 16; o > 0; o >>= 1) sd += __shfl_xor_sync(0xffffffffu, sd, o);
        float mask = (sd != 0.f) ? 1.f : 0.f;
        acc = fmaf(Wrel[r], delta + st*mask, acc);
    }
    out[(size_t)n*Cc + l] = acc;
}

// ---------------- launcher ----------------------------------------------------
extern "C" void kernel_launch(void* const* d_in, const int* in_sizes, int n_in,
                              void* d_out, int out_size) {
    const float* x     = (const float*)d_in[0];
    const void*  ei    = d_in[1];
    const void*  et    = d_in[2];
    const float* Wj    = (const float*)d_in[3];
    const float* Wi    = (const float*)d_in[4];
    const float* natt  = (const float*)d_in[5];
    const float* Wq    = (const float*)d_in[6];
    const float* Wk    = (const float*)d_in[7];
    const float* Wv    = (const float*)d_in[8];
    const float* Wself = (const float*)d_in[9];
    const float* Wsn   = (const float*)d_in[10];
    const float* Wrel  = (const float*)d_in[11];
    float* out = (float*)d_out;

    k_detect<<<1, 32>>>((const int*)ei);
    k_zero<<<400, 256>>>();
    k_convert<<<(Ee + 255)/256, 256>>>(ei, et);
    k_scan1<<<SCAN_NB, SCAN_B>>>();
    k_scan2<<<1, 512>>>();
    k_scan3<<<SCAN_NB, SCAN_B>>>();

    k_gemm_x<<<dim3(2, (Nn + 127)/128, 4), 256>>>(x, Wj, Wi, Wsn, Wself);
    k_attcoef<<<(Nn*32 + 255)/256, 256>>>(natt);
    k_reorder<<<(Ee + 255)/256, 256>>>();   // needs g_ai/g_aj
    k_seg<<<(NSEG + 7)/8, 256>>>();
    k_qkv<<<dim3((Nn + 127)/128, Rr), 256>>>(Wq, Wk, Wv);
    k_final<<<(Nn + 7)/8, 256>>>(Wrel, out);
}